// round 1
// baseline (speedup 1.0000x reference)
#include <cuda_runtime.h>

#define BATCH 32768
#define HD 128
#define OD 32
#define DEPTH 5

typedef unsigned long long ull;

// ---------- f32x2 helpers (Blackwell packed fp32 pipe) ----------
__device__ __forceinline__ ull pk2(float lo, float hi) {
    ull v; asm("mov.b64 %0, {%1, %2};" : "=l"(v) : "f"(lo), "f"(hi)); return v;
}
__device__ __forceinline__ float2 up2(ull v) {
    float2 f; asm("mov.b64 {%0, %1}, %2;" : "=f"(f.x), "=f"(f.y) : "l"(v)); return f;
}
__device__ __forceinline__ ull f2ma(ull a, ull b, ull c) {
    ull d; asm("fma.rn.f32x2 %0, %1, %2, %3;" : "=l"(d) : "l"(a), "l"(b), "l"(c)); return d;
}
__device__ __forceinline__ float sigf(float x) { return 1.0f / (1.0f + __expf(-x)); }

// ---------- per-level scratch (recursion stacks) ----------
__device__ float g_hA[DEPTH + 1][BATCH * HD];   // hidden entering rec() at level L
__device__ float g_hF[DEPTH][BATCH * HD];       // fraternal hidden at level L
__device__ float g_pr[DEPTH + 1][BATCH * OD];   // softmax probs of node at level L

// =====================================================================
// init: hidden0 = z @ z2h_w + b        [B,128] @ [128,128]
// 128 threads (g = output col), 16 rows/block, f32x2 row pairs
// =====================================================================
__global__ __launch_bounds__(128, 4)
void init_kernel(const float* __restrict__ z, const float* __restrict__ w,
                 const float* __restrict__ b, float* __restrict__ hout)
{
    const int g = threadIdx.x;
    const int row0 = blockIdx.x * 16;
    __shared__ __align__(16) ull s2[HD][10];

#pragma unroll
    for (int r = 0; r < 16; r++) {
        ((float*)&s2[g][r >> 1])[r & 1] = z[(row0 + r) * HD + g];
    }
    __syncthreads();

    ull A[8];
#pragma unroll
    for (int p = 0; p < 8; p++) A[p] = 0ull;

    float wv = __ldg(w + g);
#pragma unroll 2
    for (int j = 0; j < HD; j++) {
        int jn = (j + 1) & (HD - 1);
        float nw = __ldg(w + jn * HD + g);
        ull W = pk2(wv, wv);
#pragma unroll
        for (int q = 0; q < 4; q++) {
            ulonglong2 hv = *(const ulonglong2*)&s2[j][2 * q];
            A[2 * q]     = f2ma(hv.x, W, A[2 * q]);
            A[2 * q + 1] = f2ma(hv.y, W, A[2 * q + 1]);
        }
        wv = nw;
    }

    float bg = __ldg(b + g);
#pragma unroll
    for (int p = 0; p < 8; p++) {
        float2 a = up2(A[p]);
        hout[(row0 + 2 * p) * HD + g]     = a.x + bg;
        hout[(row0 + 2 * p + 1) * HD + g] = a.y + bg;
    }
}

// =====================================================================
// node: pred = h @ h2o_w + b ; probs = softmax(pred)   [B,128] -> [B,32]
// 128 threads: o = tid&31, row-quarter = tid>>5 ; 64 rows/block
// =====================================================================
__global__ __launch_bounds__(128, 6)
void node_kernel(const float* __restrict__ h, const float* __restrict__ w,
                 const float* __restrict__ b,
                 float* __restrict__ pred, float* __restrict__ probs)
{
    const int tid = threadIdx.x;
    const int o = tid & 31;
    const int rq = tid >> 5;
    const int row0 = blockIdx.x * 64;
    __shared__ __align__(16) ull sht2[HD][34];   // [j][row-pair], 64 rows = 32 pairs

    for (int i = tid; i < 64 * HD; i += 128) {
        int r = i >> 7, j = i & 127;
        ((float*)&sht2[j][r >> 1])[r & 1] = h[(row0 + r) * HD + j];
    }
    __syncthreads();

    ull acc[8];
#pragma unroll
    for (int p = 0; p < 8; p++) acc[p] = 0ull;

    float wv = __ldg(w + o);   // h2o_w[j][o], j=0
#pragma unroll 2
    for (int j = 0; j < HD; j++) {
        int jn = (j + 1) & (HD - 1);
        float nw = __ldg(w + jn * OD + o);
        ull W = pk2(wv, wv);
#pragma unroll
        for (int q = 0; q < 4; q++) {
            ulonglong2 hv = *(const ulonglong2*)&sht2[j][rq * 8 + 2 * q];
            acc[2 * q]     = f2ma(hv.x, W, acc[2 * q]);
            acc[2 * q + 1] = f2ma(hv.y, W, acc[2 * q + 1]);
        }
        wv = nw;
    }

    float bo = __ldg(b + o);
#pragma unroll
    for (int p = 0; p < 8; p++) {
        float2 a = up2(acc[p]);
        int r0 = row0 + rq * 16 + 2 * p;
        float v0 = a.x + bo, v1 = a.y + bo;
        pred[(size_t)r0 * OD + o]       = v0;
        pred[(size_t)(r0 + 1) * OD + o] = v1;

        float m0 = v0, m1 = v1;
#pragma unroll
        for (int s = 16; s > 0; s >>= 1) {
            m0 = fmaxf(m0, __shfl_xor_sync(0xffffffffu, m0, s));
            m1 = fmaxf(m1, __shfl_xor_sync(0xffffffffu, m1, s));
        }
        float e0 = __expf(v0 - m0), e1 = __expf(v1 - m1);
        float s0 = e0, s1 = e1;
#pragma unroll
        for (int s = 16; s > 0; s >>= 1) {
            s0 += __shfl_xor_sync(0xffffffffu, s0, s);
            s1 += __shfl_xor_sync(0xffffffffu, s1, s);
        }
        probs[(size_t)r0 * OD + o]       = e0 / s0;
        probs[(size_t)(r0 + 1) * OD + o] = e1 / s1;
    }
}

// =====================================================================
// gru: x[B,32], h[B,128] -> hn[B,128]
//   gi[k] = x@wi[k] + bi[k] ; gh[k] = h@wh[k] + bh[k]
//   r=sig(gi0+gh0) z=sig(gi1+gh1) n=tanh(gi2 + r*gh2) ; hn=(1-z)n + z h
// 128 threads (g), 16 rows/block; 4 acc sets (r-sum, z-sum, gh2, gi2)
// =====================================================================
__global__ __launch_bounds__(128, 4)
void gru_kernel(const float* __restrict__ x, const float* __restrict__ h,
                const float* __restrict__ wi, const float* __restrict__ wh,
                const float* __restrict__ bi, const float* __restrict__ bh,
                float* __restrict__ hn)
{
    const int g = threadIdx.x;
    const int row0 = blockIdx.x * 16;
    __shared__ __align__(16) ull sh2[HD][10];
    __shared__ __align__(16) ull sx2[OD][10];

#pragma unroll
    for (int r = 0; r < 16; r++) {
        ((float*)&sh2[g][r >> 1])[r & 1] = h[(row0 + r) * HD + g];
    }
#pragma unroll
    for (int i = threadIdx.x; i < 16 * OD; i += 128) {
        int r = i >> 5, o = i & 31;
        ((float*)&sx2[o][r >> 1])[r & 1] = x[(row0 + r) * OD + o];
    }
    __syncthreads();

    ull A0[8], A1[8], GH[8], GI[8];
#pragma unroll
    for (int p = 0; p < 8; p++) { A0[p] = 0ull; A1[p] = 0ull; GH[p] = 0ull; GI[p] = 0ull; }

    // ---- hidden part: K = 128, gates r,z,n-hh ----
    float w0 = __ldg(wh + g);
    float w1 = __ldg(wh + HD * HD + g);
    float w2 = __ldg(wh + 2 * HD * HD + g);
#pragma unroll 2
    for (int j = 0; j < HD; j++) {
        int jn = (j + 1) & (HD - 1);
        float n0 = __ldg(wh + jn * HD + g);
        float n1 = __ldg(wh + HD * HD + jn * HD + g);
        float n2 = __ldg(wh + 2 * HD * HD + jn * HD + g);
        ull W0 = pk2(w0, w0), W1 = pk2(w1, w1), W2 = pk2(w2, w2);
#pragma unroll
        for (int q = 0; q < 4; q++) {
            ulonglong2 hv = *(const ulonglong2*)&sh2[j][2 * q];
            A0[2 * q]     = f2ma(hv.x, W0, A0[2 * q]);
            A1[2 * q]     = f2ma(hv.x, W1, A1[2 * q]);
            GH[2 * q]     = f2ma(hv.x, W2, GH[2 * q]);
            A0[2 * q + 1] = f2ma(hv.y, W0, A0[2 * q + 1]);
            A1[2 * q + 1] = f2ma(hv.y, W1, A1[2 * q + 1]);
            GH[2 * q + 1] = f2ma(hv.y, W2, GH[2 * q + 1]);
        }
        w0 = n0; w1 = n1; w2 = n2;
    }

    // ---- input part: K = 32 ----
    w0 = __ldg(wi + g);
    w1 = __ldg(wi + OD * HD + g);
    w2 = __ldg(wi + 2 * OD * HD + g);
#pragma unroll 2
    for (int o = 0; o < OD; o++) {
        int on = (o + 1) & (OD - 1);
        float n0 = __ldg(wi + on * HD + g);
        float n1 = __ldg(wi + OD * HD + on * HD + g);
        float n2 = __ldg(wi + 2 * OD * HD + on * HD + g);
        ull W0 = pk2(w0, w0), W1 = pk2(w1, w1), W2 = pk2(w2, w2);
#pragma unroll
        for (int q = 0; q < 4; q++) {
            ulonglong2 xv = *(const ulonglong2*)&sx2[o][2 * q];
            A0[2 * q]     = f2ma(xv.x, W0, A0[2 * q]);
            A1[2 * q]     = f2ma(xv.x, W1, A1[2 * q]);
            GI[2 * q]     = f2ma(xv.x, W2, GI[2 * q]);
            A0[2 * q + 1] = f2ma(xv.y, W0, A0[2 * q + 1]);
            A1[2 * q + 1] = f2ma(xv.y, W1, A1[2 * q + 1]);
            GI[2 * q + 1] = f2ma(xv.y, W2, GI[2 * q + 1]);
        }
        w0 = n0; w1 = n1; w2 = n2;
    }

    float b0  = __ldg(bi + g)          + __ldg(bh + g);
    float b1  = __ldg(bi + HD + g)     + __ldg(bh + HD + g);
    float bi2 = __ldg(bi + 2 * HD + g);
    float bh2 = __ldg(bh + 2 * HD + g);

#pragma unroll
    for (int p = 0; p < 8; p++) {
        float2 a0 = up2(A0[p]), a1 = up2(A1[p]);
        float2 gh2 = up2(GH[p]), gi2 = up2(GI[p]);
        float2 hold = up2(sh2[g][p]);   // rows (2p, 2p+1), column g
        {
            float rr = sigf(a0.x + b0);
            float zz = sigf(a1.x + b1);
            float nn = tanhf(gi2.x + bi2 + rr * (gh2.x + bh2));
            hn[(row0 + 2 * p) * HD + g] = (1.0f - zz) * nn + zz * hold.x;
        }
        {
            float rr = sigf(a0.y + b0);
            float zz = sigf(a1.y + b1);
            float nn = tanhf(gi2.y + bi2 + rr * (gh2.y + bh2));
            hn[(row0 + 2 * p + 1) * HD + g] = (1.0f - zz) * nn + zz * hold.y;
        }
    }
}

// =====================================================================
// comb: hout = tanh(hf @ uf_w + uf_b + ha @ ua_w + ua_b)
// =====================================================================
__global__ __launch_bounds__(128, 4)
void comb_kernel(const float* __restrict__ hf, const float* __restrict__ ha,
                 const float* __restrict__ uf_w, const float* __restrict__ uf_b,
                 const float* __restrict__ ua_w, const float* __restrict__ ua_b,
                 float* __restrict__ hout)
{
    const int g = threadIdx.x;
    const int row0 = blockIdx.x * 16;
    __shared__ __align__(16) ull sf2[HD][10];
    __shared__ __align__(16) ull sa2[HD][10];

#pragma unroll
    for (int r = 0; r < 16; r++) {
        ((float*)&sf2[g][r >> 1])[r & 1] = hf[(row0 + r) * HD + g];
        ((float*)&sa2[g][r >> 1])[r & 1] = ha[(row0 + r) * HD + g];
    }
    __syncthreads();

    ull A[8];
#pragma unroll
    for (int p = 0; p < 8; p++) A[p] = 0ull;

    float wv = __ldg(uf_w + g);
#pragma unroll 2
    for (int j = 0; j < HD; j++) {
        int jn = (j + 1) & (HD - 1);
        float nw = __ldg(uf_w + jn * HD + g);
        ull W = pk2(wv, wv);
#pragma unroll
        for (int q = 0; q < 4; q++) {
            ulonglong2 hv = *(const ulonglong2*)&sf2[j][2 * q];
            A[2 * q]     = f2ma(hv.x, W, A[2 * q]);
            A[2 * q + 1] = f2ma(hv.y, W, A[2 * q + 1]);
        }
        wv = nw;
    }
    wv = __ldg(ua_w + g);
#pragma unroll 2
    for (int j = 0; j < HD; j++) {
        int jn = (j + 1) & (HD - 1);
        float nw = __ldg(ua_w + jn * HD + g);
        ull W = pk2(wv, wv);
#pragma unroll
        for (int q = 0; q < 4; q++) {
            ulonglong2 hv = *(const ulonglong2*)&sa2[j][2 * q];
            A[2 * q]     = f2ma(hv.x, W, A[2 * q]);
            A[2 * q + 1] = f2ma(hv.y, W, A[2 * q + 1]);
        }
        wv = nw;
    }

    float bsum = __ldg(uf_b + g) + __ldg(ua_b + g);
#pragma unroll
    for (int p = 0; p < 8; p++) {
        float2 a = up2(A[p]);
        hout[(row0 + 2 * p) * HD + g]     = tanhf(a.x + bsum);
        hout[(row0 + 2 * p + 1) * HD + g] = tanhf(a.y + bsum);
    }
}

// =====================================================================
// host-side preorder recursion -> launch sequence (graph-capturable)
// =====================================================================
namespace {

struct LCtx {
    const float *h2o_w, *h2o_b;
    const float *anc_wi, *anc_wh, *anc_bi, *anc_bh;
    const float *frat_wi, *frat_wh, *frat_bi, *frat_bh;
    const float *ua_w, *ua_b, *uf_w, *uf_b;
    float *hA, *hF, *pr, *out;
    int idx;
};

void rec(LCtx& c, int L, int d)
{
    // node: pred + softmax from hA[L]
    node_kernel<<<BATCH / 64, 128>>>(c.hA + (size_t)L * BATCH * HD,
                                     c.h2o_w, c.h2o_b,
                                     c.out + (size_t)c.idx * BATCH * OD,
                                     c.pr + (size_t)L * BATCH * OD);
    c.idx++;
    if (d == 0) return;

    // ancestral GRU -> hidden for first child
    gru_kernel<<<BATCH / 16, 128>>>(c.pr + (size_t)L * BATCH * OD,
                                    c.hA + (size_t)L * BATCH * HD,
                                    c.anc_wi, c.anc_wh, c.anc_bi, c.anc_bh,
                                    c.hA + (size_t)(L + 1) * BATCH * HD);
    rec(c, L + 1, d - 1);

    // fraternal GRU consumes first child's probs (pr[L+1]) and h_ai (hA[L+1])
    gru_kernel<<<BATCH / 16, 128>>>(c.pr + (size_t)(L + 1) * BATCH * OD,
                                    c.hA + (size_t)(L + 1) * BATCH * HD,
                                    c.frat_wi, c.frat_wh, c.frat_bi, c.frat_bh,
                                    c.hF + (size_t)L * BATCH * HD);

    // hidden = tanh(hf@uf + ha@ua + biases) -> hidden for second child
    comb_kernel<<<BATCH / 16, 128>>>(c.hF + (size_t)L * BATCH * HD,
                                     c.hA + (size_t)L * BATCH * HD,
                                     c.uf_w, c.uf_b, c.ua_w, c.ua_b,
                                     c.hA + (size_t)(L + 1) * BATCH * HD);
    rec(c, L + 1, d - 1);
}

} // namespace

extern "C" void kernel_launch(void* const* d_in, const int* in_sizes, int n_in,
                              void* d_out, int out_size)
{
    const float* z       = (const float*)d_in[0];
    const float* z2h_w   = (const float*)d_in[1];
    const float* z2h_b   = (const float*)d_in[2];
    const float* h2o_w   = (const float*)d_in[3];
    const float* h2o_b   = (const float*)d_in[4];
    const float* anc_wi  = (const float*)d_in[5];
    const float* anc_wh  = (const float*)d_in[6];
    const float* anc_bi  = (const float*)d_in[7];
    const float* anc_bh  = (const float*)d_in[8];
    const float* frat_wi = (const float*)d_in[9];
    const float* frat_wh = (const float*)d_in[10];
    const float* frat_bi = (const float*)d_in[11];
    const float* frat_bh = (const float*)d_in[12];
    const float* ua_w    = (const float*)d_in[13];
    const float* ua_b    = (const float*)d_in[14];
    const float* uf_w    = (const float*)d_in[15];
    const float* uf_b    = (const float*)d_in[16];
    // d_in[17] = depth (5), d_in[18] = arity (2): fixed by problem shape.

    float *hA, *hF, *pr;
    cudaGetSymbolAddress((void**)&hA, g_hA);
    cudaGetSymbolAddress((void**)&hF, g_hF);
    cudaGetSymbolAddress((void**)&pr, g_pr);

    // hidden0 = z @ z2h_w + z2h_b
    init_kernel<<<BATCH / 16, 128>>>(z, z2h_w, z2h_b, hA);

    LCtx c;
    c.h2o_w = h2o_w; c.h2o_b = h2o_b;
    c.anc_wi = anc_wi; c.anc_wh = anc_wh; c.anc_bi = anc_bi; c.anc_bh = anc_bh;
    c.frat_wi = frat_wi; c.frat_wh = frat_wh; c.frat_bi = frat_bi; c.frat_bh = frat_bh;
    c.ua_w = ua_w; c.ua_b = ua_b; c.uf_w = uf_w; c.uf_b = uf_b;
    c.hA = hA; c.hF = hF; c.pr = pr;
    c.out = (float*)d_out;
    c.idx = 0;

    rec(c, 0, DEPTH);
}

// round 2
// speedup vs baseline: 1.0048x; 1.0048x over previous
#include <cuda_runtime.h>

#define BATCH 32768
#define HD 128
#define OD 32
#define DEPTH 5

typedef unsigned long long ull;

// ---------- f32x2 helpers (Blackwell packed fp32 pipe) ----------
__device__ __forceinline__ ull pk2(float lo, float hi) {
    ull v; asm("mov.b64 %0, {%1, %2};" : "=l"(v) : "f"(lo), "f"(hi)); return v;
}
__device__ __forceinline__ float2 up2(ull v) {
    float2 f; asm("mov.b64 {%0, %1}, %2;" : "=f"(f.x), "=f"(f.y) : "l"(v)); return f;
}
__device__ __forceinline__ ull f2ma(ull a, ull b, ull c) {
    ull d; asm("fma.rn.f32x2 %0, %1, %2, %3;" : "=l"(d) : "l"(a), "l"(b), "l"(c)); return d;
}
__device__ __forceinline__ float sigf(float x) { return 1.0f / (1.0f + __expf(-x)); }

// ---------- per-level scratch (recursion stacks) ----------
__device__ float g_hA[DEPTH + 1][BATCH * HD];   // hidden entering rec() at level L
__device__ float g_hF[DEPTH][BATCH * HD];       // fraternal hidden at level L
__device__ float g_pr[DEPTH + 1][BATCH * OD];   // softmax probs of node at level L

// =====================================================================
// init: hidden0 = z @ z2h_w + b        [B,128] @ [128,128]
// 128 threads (g = output col), 16 rows/block, f32x2 row pairs
// =====================================================================
__global__ __launch_bounds__(128, 4)
void init_kernel(const float* __restrict__ z, const float* __restrict__ w,
                 const float* __restrict__ b, float* __restrict__ hout)
{
    const int g = threadIdx.x;
    const int row0 = blockIdx.x * 16;
    __shared__ __align__(16) ull s2[HD][10];

#pragma unroll
    for (int r = 0; r < 16; r++) {
        ((float*)&s2[g][r >> 1])[r & 1] = z[(row0 + r) * HD + g];
    }
    __syncthreads();

    ull A[8];
#pragma unroll
    for (int p = 0; p < 8; p++) A[p] = 0ull;

    float wv = __ldg(w + g);
#pragma unroll 2
    for (int j = 0; j < HD; j++) {
        int jn = (j + 1) & (HD - 1);
        float nw = __ldg(w + jn * HD + g);
        ull W = pk2(wv, wv);
#pragma unroll
        for (int q = 0; q < 4; q++) {
            ulonglong2 hv = *(const ulonglong2*)&s2[j][2 * q];
            A[2 * q]     = f2ma(hv.x, W, A[2 * q]);
            A[2 * q + 1] = f2ma(hv.y, W, A[2 * q + 1]);
        }
        wv = nw;
    }

    float bg = __ldg(b + g);
#pragma unroll
    for (int p = 0; p < 8; p++) {
        float2 a = up2(A[p]);
        hout[(row0 + 2 * p) * HD + g]     = a.x + bg;
        hout[(row0 + 2 * p + 1) * HD + g] = a.y + bg;
    }
}

// =====================================================================
// node: pred = h @ h2o_w + b ; probs = softmax(pred)   [B,128] -> [B,32]
// 128 threads: o = tid&31, row-quarter = tid>>5 ; 64 rows/block
// =====================================================================
__global__ __launch_bounds__(128, 6)
void node_kernel(const float* __restrict__ h, const float* __restrict__ w,
                 const float* __restrict__ b,
                 float* __restrict__ pred, float* __restrict__ probs)
{
    const int tid = threadIdx.x;
    const int o = tid & 31;
    const int rq = tid >> 5;
    const int row0 = blockIdx.x * 64;
    __shared__ __align__(16) ull sht2[HD][34];   // [j][row-pair], 64 rows = 32 pairs

    for (int i = tid; i < 64 * HD; i += 128) {
        int r = i >> 7, j = i & 127;
        ((float*)&sht2[j][r >> 1])[r & 1] = h[(row0 + r) * HD + j];
    }
    __syncthreads();

    ull acc[8];
#pragma unroll
    for (int p = 0; p < 8; p++) acc[p] = 0ull;

    float wv = __ldg(w + o);   // h2o_w[j][o], j=0
#pragma unroll 2
    for (int j = 0; j < HD; j++) {
        int jn = (j + 1) & (HD - 1);
        float nw = __ldg(w + jn * OD + o);
        ull W = pk2(wv, wv);
#pragma unroll
        for (int q = 0; q < 4; q++) {
            ulonglong2 hv = *(const ulonglong2*)&sht2[j][rq * 8 + 2 * q];
            acc[2 * q]     = f2ma(hv.x, W, acc[2 * q]);
            acc[2 * q + 1] = f2ma(hv.y, W, acc[2 * q + 1]);
        }
        wv = nw;
    }

    float bo = __ldg(b + o);
#pragma unroll
    for (int p = 0; p < 8; p++) {
        float2 a = up2(acc[p]);
        int r0 = row0 + rq * 16 + 2 * p;
        float v0 = a.x + bo, v1 = a.y + bo;
        pred[(size_t)r0 * OD + o]       = v0;
        pred[(size_t)(r0 + 1) * OD + o] = v1;

        float m0 = v0, m1 = v1;
#pragma unroll
        for (int s = 16; s > 0; s >>= 1) {
            m0 = fmaxf(m0, __shfl_xor_sync(0xffffffffu, m0, s));
            m1 = fmaxf(m1, __shfl_xor_sync(0xffffffffu, m1, s));
        }
        float e0 = __expf(v0 - m0), e1 = __expf(v1 - m1);
        float s0 = e0, s1 = e1;
#pragma unroll
        for (int s = 16; s > 0; s >>= 1) {
            s0 += __shfl_xor_sync(0xffffffffu, s0, s);
            s1 += __shfl_xor_sync(0xffffffffu, s1, s);
        }
        probs[(size_t)r0 * OD + o]       = e0 / s0;
        probs[(size_t)(r0 + 1) * OD + o] = e1 / s1;
    }
}

// =====================================================================
// gru: x[B,32], h[B,128] -> hn[B,128]
//   gi[k] = x@wi[k] + bi[k] ; gh[k] = h@wh[k] + bh[k]
//   r=sig(gi0+gh0) z=sig(gi1+gh1) n=tanh(gi2 + r*gh2) ; hn=(1-z)n + z h
// 128 threads (g), 16 rows/block; 4 acc sets (r-sum, z-sum, gh2, gi2)
// =====================================================================
__global__ __launch_bounds__(128, 4)
void gru_kernel(const float* __restrict__ x, const float* __restrict__ h,
                const float* __restrict__ wi, const float* __restrict__ wh,
                const float* __restrict__ bi, const float* __restrict__ bh,
                float* __restrict__ hn)
{
    const int g = threadIdx.x;
    const int row0 = blockIdx.x * 16;
    __shared__ __align__(16) ull sh2[HD][10];
    __shared__ __align__(16) ull sx2[OD][10];

#pragma unroll
    for (int r = 0; r < 16; r++) {
        ((float*)&sh2[g][r >> 1])[r & 1] = h[(row0 + r) * HD + g];
    }
#pragma unroll
    for (int i = threadIdx.x; i < 16 * OD; i += 128) {
        int r = i >> 5, o = i & 31;
        ((float*)&sx2[o][r >> 1])[r & 1] = x[(row0 + r) * OD + o];
    }
    __syncthreads();

    ull A0[8], A1[8], GH[8], GI[8];
#pragma unroll
    for (int p = 0; p < 8; p++) { A0[p] = 0ull; A1[p] = 0ull; GH[p] = 0ull; GI[p] = 0ull; }

    // ---- hidden part: K = 128, gates r,z,n-hh ----
    float w0 = __ldg(wh + g);
    float w1 = __ldg(wh + HD * HD + g);
    float w2 = __ldg(wh + 2 * HD * HD + g);
#pragma unroll 2
    for (int j = 0; j < HD; j++) {
        int jn = (j + 1) & (HD - 1);
        float n0 = __ldg(wh + jn * HD + g);
        float n1 = __ldg(wh + HD * HD + jn * HD + g);
        float n2 = __ldg(wh + 2 * HD * HD + jn * HD + g);
        ull W0 = pk2(w0, w0), W1 = pk2(w1, w1), W2 = pk2(w2, w2);
#pragma unroll
        for (int q = 0; q < 4; q++) {
            ulonglong2 hv = *(const ulonglong2*)&sh2[j][2 * q];
            A0[2 * q]     = f2ma(hv.x, W0, A0[2 * q]);
            A1[2 * q]     = f2ma(hv.x, W1, A1[2 * q]);
            GH[2 * q]     = f2ma(hv.x, W2, GH[2 * q]);
            A0[2 * q + 1] = f2ma(hv.y, W0, A0[2 * q + 1]);
            A1[2 * q + 1] = f2ma(hv.y, W1, A1[2 * q + 1]);
            GH[2 * q + 1] = f2ma(hv.y, W2, GH[2 * q + 1]);
        }
        w0 = n0; w1 = n1; w2 = n2;
    }

    // ---- input part: K = 32 ----
    w0 = __ldg(wi + g);
    w1 = __ldg(wi + OD * HD + g);
    w2 = __ldg(wi + 2 * OD * HD + g);
#pragma unroll 2
    for (int o = 0; o < OD; o++) {
        int on = (o + 1) & (OD - 1);
        float n0 = __ldg(wi + on * HD + g);
        float n1 = __ldg(wi + OD * HD + on * HD + g);
        float n2 = __ldg(wi + 2 * OD * HD + on * HD + g);
        ull W0 = pk2(w0, w0), W1 = pk2(w1, w1), W2 = pk2(w2, w2);
#pragma unroll
        for (int q = 0; q < 4; q++) {
            ulonglong2 xv = *(const ulonglong2*)&sx2[o][2 * q];
            A0[2 * q]     = f2ma(xv.x, W0, A0[2 * q]);
            A1[2 * q]     = f2ma(xv.x, W1, A1[2 * q]);
            GI[2 * q]     = f2ma(xv.x, W2, GI[2 * q]);
            A0[2 * q + 1] = f2ma(xv.y, W0, A0[2 * q + 1]);
            A1[2 * q + 1] = f2ma(xv.y, W1, A1[2 * q + 1]);
            GI[2 * q + 1] = f2ma(xv.y, W2, GI[2 * q + 1]);
        }
        w0 = n0; w1 = n1; w2 = n2;
    }

    float b0  = __ldg(bi + g)          + __ldg(bh + g);
    float b1  = __ldg(bi + HD + g)     + __ldg(bh + HD + g);
    float bi2 = __ldg(bi + 2 * HD + g);
    float bh2 = __ldg(bh + 2 * HD + g);

#pragma unroll
    for (int p = 0; p < 8; p++) {
        float2 a0 = up2(A0[p]), a1 = up2(A1[p]);
        float2 gh2 = up2(GH[p]), gi2 = up2(GI[p]);
        float2 hold = up2(sh2[g][p]);   // rows (2p, 2p+1), column g
        {
            float rr = sigf(a0.x + b0);
            float zz = sigf(a1.x + b1);
            float nn = tanhf(gi2.x + bi2 + rr * (gh2.x + bh2));
            hn[(row0 + 2 * p) * HD + g] = (1.0f - zz) * nn + zz * hold.x;
        }
        {
            float rr = sigf(a0.y + b0);
            float zz = sigf(a1.y + b1);
            float nn = tanhf(gi2.y + bi2 + rr * (gh2.y + bh2));
            hn[(row0 + 2 * p + 1) * HD + g] = (1.0f - zz) * nn + zz * hold.y;
        }
    }
}

// =====================================================================
// comb: hout = tanh(hf @ uf_w + uf_b + ha @ ua_w + ua_b)
// =====================================================================
__global__ __launch_bounds__(128, 4)
void comb_kernel(const float* __restrict__ hf, const float* __restrict__ ha,
                 const float* __restrict__ uf_w, const float* __restrict__ uf_b,
                 const float* __restrict__ ua_w, const float* __restrict__ ua_b,
                 float* __restrict__ hout)
{
    const int g = threadIdx.x;
    const int row0 = blockIdx.x * 16;
    __shared__ __align__(16) ull sf2[HD][10];
    __shared__ __align__(16) ull sa2[HD][10];

#pragma unroll
    for (int r = 0; r < 16; r++) {
        ((float*)&sf2[g][r >> 1])[r & 1] = hf[(row0 + r) * HD + g];
        ((float*)&sa2[g][r >> 1])[r & 1] = ha[(row0 + r) * HD + g];
    }
    __syncthreads();

    ull A[8];
#pragma unroll
    for (int p = 0; p < 8; p++) A[p] = 0ull;

    float wv = __ldg(uf_w + g);
#pragma unroll 2
    for (int j = 0; j < HD; j++) {
        int jn = (j + 1) & (HD - 1);
        float nw = __ldg(uf_w + jn * HD + g);
        ull W = pk2(wv, wv);
#pragma unroll
        for (int q = 0; q < 4; q++) {
            ulonglong2 hv = *(const ulonglong2*)&sf2[j][2 * q];
            A[2 * q]     = f2ma(hv.x, W, A[2 * q]);
            A[2 * q + 1] = f2ma(hv.y, W, A[2 * q + 1]);
        }
        wv = nw;
    }
    wv = __ldg(ua_w + g);
#pragma unroll 2
    for (int j = 0; j < HD; j++) {
        int jn = (j + 1) & (HD - 1);
        float nw = __ldg(ua_w + jn * HD + g);
        ull W = pk2(wv, wv);
#pragma unroll
        for (int q = 0; q < 4; q++) {
            ulonglong2 hv = *(const ulonglong2*)&sa2[j][2 * q];
            A[2 * q]     = f2ma(hv.x, W, A[2 * q]);
            A[2 * q + 1] = f2ma(hv.y, W, A[2 * q + 1]);
        }
        wv = nw;
    }

    float bsum = __ldg(uf_b + g) + __ldg(ua_b + g);
#pragma unroll
    for (int p = 0; p < 8; p++) {
        float2 a = up2(A[p]);
        hout[(row0 + 2 * p) * HD + g]     = tanhf(a.x + bsum);
        hout[(row0 + 2 * p + 1) * HD + g] = tanhf(a.y + bsum);
    }
}

// =====================================================================
// host-side preorder recursion -> launch sequence (graph-capturable)
// =====================================================================
namespace {

struct LCtx {
    const float *h2o_w, *h2o_b;
    const float *anc_wi, *anc_wh, *anc_bi, *anc_bh;
    const float *frat_wi, *frat_wh, *frat_bi, *frat_bh;
    const float *ua_w, *ua_b, *uf_w, *uf_b;
    float *hA, *hF, *pr, *out;
    int idx;
};

void rec(LCtx& c, int L, int d)
{
    // node: pred + softmax from hA[L]
    node_kernel<<<BATCH / 64, 128>>>(c.hA + (size_t)L * BATCH * HD,
                                     c.h2o_w, c.h2o_b,
                                     c.out + (size_t)c.idx * BATCH * OD,
                                     c.pr + (size_t)L * BATCH * OD);
    c.idx++;
    if (d == 0) return;

    // ancestral GRU -> hidden for first child
    gru_kernel<<<BATCH / 16, 128>>>(c.pr + (size_t)L * BATCH * OD,
                                    c.hA + (size_t)L * BATCH * HD,
                                    c.anc_wi, c.anc_wh, c.anc_bi, c.anc_bh,
                                    c.hA + (size_t)(L + 1) * BATCH * HD);
    rec(c, L + 1, d - 1);

    // fraternal GRU consumes first child's probs (pr[L+1]) and h_ai (hA[L+1])
    gru_kernel<<<BATCH / 16, 128>>>(c.pr + (size_t)(L + 1) * BATCH * OD,
                                    c.hA + (size_t)(L + 1) * BATCH * HD,
                                    c.frat_wi, c.frat_wh, c.frat_bi, c.frat_bh,
                                    c.hF + (size_t)L * BATCH * HD);

    // hidden = tanh(hf@uf + ha@ua + biases) -> hidden for second child
    comb_kernel<<<BATCH / 16, 128>>>(c.hF + (size_t)L * BATCH * HD,
                                     c.hA + (size_t)L * BATCH * HD,
                                     c.uf_w, c.uf_b, c.ua_w, c.ua_b,
                                     c.hA + (size_t)(L + 1) * BATCH * HD);
    rec(c, L + 1, d - 1);
}

} // namespace

extern "C" void kernel_launch(void* const* d_in, const int* in_sizes, int n_in,
                              void* d_out, int out_size)
{
    const float* z       = (const float*)d_in[0];
    const float* z2h_w   = (const float*)d_in[1];
    const float* z2h_b   = (const float*)d_in[2];
    const float* h2o_w   = (const float*)d_in[3];
    const float* h2o_b   = (const float*)d_in[4];
    const float* anc_wi  = (const float*)d_in[5];
    const float* anc_wh  = (const float*)d_in[6];
    const float* anc_bi  = (const float*)d_in[7];
    const float* anc_bh  = (const float*)d_in[8];
    const float* frat_wi = (const float*)d_in[9];
    const float* frat_wh = (const float*)d_in[10];
    const float* frat_bi = (const float*)d_in[11];
    const float* frat_bh = (const float*)d_in[12];
    const float* ua_w    = (const float*)d_in[13];
    const float* ua_b    = (const float*)d_in[14];
    const float* uf_w    = (const float*)d_in[15];
    const float* uf_b    = (const float*)d_in[16];
    // d_in[17] = depth (5), d_in[18] = arity (2): fixed by problem shape.

    float *hA, *hF, *pr;
    cudaGetSymbolAddress((void**)&hA, g_hA);
    cudaGetSymbolAddress((void**)&hF, g_hF);
    cudaGetSymbolAddress((void**)&pr, g_pr);

    // hidden0 = z @ z2h_w + z2h_b
    init_kernel<<<BATCH / 16, 128>>>(z, z2h_w, z2h_b, hA);

    LCtx c;
    c.h2o_w = h2o_w; c.h2o_b = h2o_b;
    c.anc_wi = anc_wi; c.anc_wh = anc_wh; c.anc_bi = anc_bi; c.anc_bh = anc_bh;
    c.frat_wi = frat_wi; c.frat_wh = frat_wh; c.frat_bi = frat_bi; c.frat_bh = frat_bh;
    c.ua_w = ua_w; c.ua_b = ua_b; c.uf_w = uf_w; c.uf_b = uf_b;
    c.hA = hA; c.hF = hF; c.pr = pr;
    c.out = (float*)d_out;
    c.idx = 0;

    rec(c, 0, DEPTH);
}

// round 5
// speedup vs baseline: 2.2370x; 2.2264x over previous
#include <cuda_runtime.h>
#include <cuda_fp16.h>
#include <cstdint>

#define BATCH 32768
#define HD 128
#define OD 32
#define DEPTH 5
typedef uint32_t u32;

// ---- weight tile offsets in g_wt (halves) ----
#define W_ANC_WH  0
#define W_FRAT_WH 98304
#define W_ANC_WI  196608
#define W_FRAT_WI 221184
#define W_UF      245760
#define W_UA      278528
#define W_H2O     311296
__device__ __half g_wt[319488];

__device__ __half g_hAh[DEPTH + 1][BATCH * HD];
__device__ __half g_hAl[DEPTH + 1][BATCH * HD];
__device__ __half g_hFh[DEPTH][BATCH * HD];
__device__ __half g_hFl[DEPTH][BATCH * HD];
__device__ __half g_prh[DEPTH + 1][BATCH * OD];
__device__ __half g_prl[DEPTH + 1][BATCH * OD];

// ===================== helpers =====================
__device__ __forceinline__ u32 smaddr(const void* p) {
    u32 a;
    asm("{ .reg .u64 t; cvta.to.shared.u64 t, %1; cvt.u32.u64 %0, t; }" : "=r"(a) : "l"(p));
    return a;
}
__device__ __forceinline__ void cpa16(u32 d, const void* s) {
    asm volatile("cp.async.cg.shared.global [%0], [%1], 16;" :: "r"(d), "l"(s) : "memory");
}
__device__ __forceinline__ void cpwait() {
    asm volatile("cp.async.commit_group;\n\tcp.async.wait_group 0;" ::: "memory");
}
__device__ __forceinline__ void ldm4(u32* r, u32 a) {
    asm volatile("ldmatrix.sync.aligned.m8n8.x4.shared.b16 {%0,%1,%2,%3}, [%4];"
                 : "=r"(r[0]), "=r"(r[1]), "=r"(r[2]), "=r"(r[3]) : "r"(a));
}
__device__ __forceinline__ void mmaf(float* c, const u32* a, const u32* b) {
    asm volatile(
        "mma.sync.aligned.m16n8k16.row.col.f32.f16.f16.f32 "
        "{%0,%1,%2,%3},{%4,%5,%6,%7},{%8,%9},{%0,%1,%2,%3};"
        : "+f"(c[0]), "+f"(c[1]), "+f"(c[2]), "+f"(c[3])
        : "r"(a[0]), "r"(a[1]), "r"(a[2]), "r"(a[3]), "r"(b[0]), "r"(b[1]));
}
__device__ __forceinline__ float fsig(float x)  { return __fdividef(1.0f, 1.0f + __expf(-x)); }
__device__ __forceinline__ float ftanh(float x) { float u = __expf(2.0f * x); return 1.0f - __fdividef(2.0f, u + 1.0f); }
__device__ __forceinline__ void wsplit(float v, __half& h, __half& l) {
    h = __float2half_rn(v);
    l = __float2half_rn(v - __half2float(h));
}

// ---- ldmatrix addressing (SW: pitch 256B, XOR r&7 ; pitch 64B, XOR r&3) ----
__device__ __forceinline__ void ldmA128(u32* r, u32 base, int m0, int lane, int kc) {
    int row = m0 + (lane & 15), c16 = 2 * kc + (lane >> 4);
    ldm4(r, base + (u32)row * 256u + (u32)((c16 ^ (row & 7)) << 4));
}
__device__ __forceinline__ void ldmB128(u32* r, u32 base, int n0, int lane, int kc) {
    int row = n0 + (lane & 7) + ((lane >> 4) << 3), c16 = 2 * kc + ((lane >> 3) & 1);
    ldm4(r, base + (u32)row * 256u + (u32)((c16 ^ (row & 7)) << 4));
}
__device__ __forceinline__ void ldmA32(u32* r, u32 base, int m0, int lane, int kc) {
    int row = m0 + (lane & 15), c4 = 2 * kc + (lane >> 4);
    ldm4(r, base + (u32)row * 64u + (u32)((c4 ^ (row & 3)) << 4));
}
__device__ __forceinline__ void ldmB32(u32* r, u32 base, int n0, int lane, int kc) {
    int row = n0 + (lane & 7) + ((lane >> 4) << 3), c4 = 2 * kc + ((lane >> 3) & 1);
    ldm4(r, base + (u32)row * 64u + (u32)((c4 ^ (row & 3)) << 4));
}

// ---- 32x64 warp tile, 3-term hi/lo, one k16 chunk ----
__device__ __forceinline__ void kstep128(float (*acc)[4], u32 AH, u32 AL, u32 BH, u32 BL,
                                         int m0, int n0, int lane, int kc) {
    u32 a[4][4];
    ldmA128(a[0], AH, m0, lane, kc);      ldmA128(a[1], AH, m0 + 16, lane, kc);
    ldmA128(a[2], AL, m0, lane, kc);      ldmA128(a[3], AL, m0 + 16, lane, kc);
#pragma unroll
    for (int G = 0; G < 4; G++) {
        u32 bh[4], bl[4];
        ldmB128(bh, BH, n0 + G * 16, lane, kc);
        ldmB128(bl, BL, n0 + G * 16, lane, kc);
#pragma unroll
        for (int mf = 0; mf < 2; mf++) {
            float* c0 = acc[mf * 8 + G * 2];
            float* c1 = acc[mf * 8 + G * 2 + 1];
            mmaf(c0, a[mf], bh);     mmaf(c1, a[mf], bh + 2);
            mmaf(c0, a[mf], bl);     mmaf(c1, a[mf], bl + 2);
            mmaf(c0, a[2 + mf], bh); mmaf(c1, a[2 + mf], bh + 2);
        }
    }
}
__device__ __forceinline__ void kstep32(float (*acc)[4], u32 AH, u32 AL, u32 BH, u32 BL,
                                        int m0, int n0, int lane, int kc) {
    u32 a[4][4];
    ldmA32(a[0], AH, m0, lane, kc);      ldmA32(a[1], AH, m0 + 16, lane, kc);
    ldmA32(a[2], AL, m0, lane, kc);      ldmA32(a[3], AL, m0 + 16, lane, kc);
#pragma unroll
    for (int G = 0; G < 4; G++) {
        u32 bh[4], bl[4];
        ldmB32(bh, BH, n0 + G * 16, lane, kc);
        ldmB32(bl, BL, n0 + G * 16, lane, kc);
#pragma unroll
        for (int mf = 0; mf < 2; mf++) {
            float* c0 = acc[mf * 8 + G * 2];
            float* c1 = acc[mf * 8 + G * 2 + 1];
            mmaf(c0, a[mf], bh);     mmaf(c1, a[mf], bh + 2);
            mmaf(c0, a[mf], bl);     mmaf(c1, a[mf], bl + 2);
            mmaf(c0, a[2 + mf], bh); mmaf(c1, a[2 + mf], bh + 2);
        }
    }
}
__device__ __forceinline__ void zacc(float (*acc)[4]) {
#pragma unroll
    for (int f = 0; f < 16; f++)
#pragma unroll
        for (int i = 0; i < 4; i++) acc[f][i] = 0.0f;
}

// ---- staging: 16B cp.async, XOR-swizzled dst ----
__device__ __forceinline__ void stage128(u32 dst, const __half* src, int rows, int tid) {
    for (int i = tid; i < rows * 16; i += 256) {
        int r = i >> 4, c = i & 15;
        cpa16(dst + (u32)r * 256u + (u32)((c ^ (r & 7)) << 4), src + (size_t)r * 128 + c * 8);
    }
}
__device__ __forceinline__ void stage32s(u32 dst, const __half* src, int tid) {
    for (int i = tid; i < 128 * 4; i += 256) {
        int r = i >> 2, c = i & 3;
        cpa16(dst + (u32)r * 64u + (u32)((c ^ (r & 3)) << 4), src + (size_t)r * 32 + c * 8);
    }
}

// ===================== prep: transpose + hi/lo split all weights =====================
__global__ void k_prep(const float* __restrict__ anc_wi, const float* __restrict__ anc_wh,
                       const float* __restrict__ frat_wi, const float* __restrict__ frat_wh,
                       const float* __restrict__ uf_w, const float* __restrict__ ua_w,
                       const float* __restrict__ h2o_w)
{
    int t = blockIdx.x * blockDim.x + threadIdx.x, NT = gridDim.x * blockDim.x;
    for (int i = t; i < 3 * 16384; i += NT) {
        int g = i >> 14, rem = i & 16383, k = rem >> 7, n = rem & 127;
        int d = g * 32768 + n * 128 + k;
        __half h, l;
        wsplit(anc_wh[i], h, l);  g_wt[W_ANC_WH + d] = h;  g_wt[W_ANC_WH + d + 16384] = l;
        wsplit(frat_wh[i], h, l); g_wt[W_FRAT_WH + d] = h; g_wt[W_FRAT_WH + d + 16384] = l;
    }
    for (int i = t; i < 3 * 4096; i += NT) {
        int g = i >> 12, rem = i & 4095, k = rem >> 7, n = rem & 127;
        int d = g * 8192 + n * 32 + k;
        __half h, l;
        wsplit(anc_wi[i], h, l);  g_wt[W_ANC_WI + d] = h;  g_wt[W_ANC_WI + d + 4096] = l;
        wsplit(frat_wi[i], h, l); g_wt[W_FRAT_WI + d] = h; g_wt[W_FRAT_WI + d + 4096] = l;
    }
    for (int i = t; i < 16384; i += NT) {
        int k = i >> 7, n = i & 127, d = n * 128 + k;
        __half h, l;
        wsplit(uf_w[i], h, l); g_wt[W_UF + d] = h; g_wt[W_UF + d + 16384] = l;
        wsplit(ua_w[i], h, l); g_wt[W_UA + d] = h; g_wt[W_UA + d + 16384] = l;
    }
    for (int i = t; i < 4096; i += NT) {
        int k = i >> 5, n = i & 31, d = n * 128 + k;
        __half h, l;
        wsplit(h2o_w[i], h, l); g_wt[W_H2O + d] = h; g_wt[W_H2O + d + 4096] = l;
    }
}

// ===================== init: hidden0 = z @ z2h_w + b (FFMA, hi/lo out) =====================
__global__ __launch_bounds__(128, 4)
void init_k(const float* __restrict__ z, const float* __restrict__ w,
            const float* __restrict__ b, __half* __restrict__ oh, __half* __restrict__ ol)
{
    const int g = threadIdx.x;
    const int row0 = blockIdx.x * 16;
    __shared__ float s[16][HD];
    for (int r = 0; r < 16; r++) s[r][g] = z[(size_t)(row0 + r) * HD + g];
    __syncthreads();
    float a[16];
#pragma unroll
    for (int r = 0; r < 16; r++) a[r] = 0.0f;
    for (int j = 0; j < HD; j++) {
        float wv = __ldg(w + (size_t)j * HD + g);
#pragma unroll
        for (int r = 0; r < 16; r++) a[r] += s[r][j] * wv;
    }
    float bg = __ldg(b + g);
#pragma unroll
    for (int r = 0; r < 16; r++) {
        __half h, l; wsplit(a[r] + bg, h, l);
        size_t o = (size_t)(row0 + r) * HD + g;
        oh[o] = h; ol[o] = l;
    }
}

// ===================== GRU fused (tensor) =====================
// SMEM byte offsets
#define oAH  0
#define oAL  32768
#define oAXH 65536
#define oAXL 73728
#define oBH  81920
#define oBL  114688
#define oBXH 147456
#define oBXL 155648
#define oRS  163840
#define oZS  196608
#define oBIA 229376
#define GRU_DS 231424

__global__ __launch_bounds__(256)
void gru_k(const __half* __restrict__ xh, const __half* __restrict__ xl,
           const __half* __restrict__ hh, const __half* __restrict__ hl,
           const __half* __restrict__ whT, const __half* __restrict__ wiT,
           const float* __restrict__ bi, const float* __restrict__ bhp,
           __half* __restrict__ oh, __half* __restrict__ ol)
{
    extern __shared__ char dsm[];
    const u32 S = smaddr(dsm);
    const int tid = threadIdx.x, lane = tid & 31, wid = tid >> 5;
    const int row0 = blockIdx.x * 128;
    const int m0 = (wid & 3) * 32, n0 = (wid >> 2) * 64;

    if (tid < 128) {
        float4 bv = make_float4(__ldg(bi + tid) + __ldg(bhp + tid),
                                __ldg(bi + 128 + tid) + __ldg(bhp + 128 + tid),
                                __ldg(bhp + 256 + tid), __ldg(bi + 256 + tid));
        *(float4*)(dsm + oBIA + tid * 16) = bv;
    }
    stage128(S + oAH, hh + (size_t)row0 * 128, 128, tid);
    stage128(S + oAL, hl + (size_t)row0 * 128, 128, tid);
    stage32s(S + oAXH, xh + (size_t)row0 * 32, tid);
    stage32s(S + oAXL, xl + (size_t)row0 * 32, tid);
    stage128(S + oBH, whT, 128, tid);
    stage128(S + oBL, whT + 16384, 128, tid);
    stage32s(S + oBXH, wiT, tid);
    stage32s(S + oBXL, wiT + 4096, tid);
    cpwait(); __syncthreads();

    const int lr = lane >> 2, lc = 2 * (lane & 3);
    float acc[16][4];

    // ---- gates r (comp 0) and z (comp 1) ----
#pragma unroll 1
    for (int gate = 0; gate < 2; gate++) {
        zacc(acc);
        for (int kc = 0; kc < 8; kc++)
            kstep128(acc, S + oAH, S + oAL, S + oBH, S + oBL, m0, n0, lane, kc);
        for (int kc = 0; kc < 2; kc++)
            kstep32(acc, S + oAXH, S + oAXL, S + oBXH, S + oBXL, m0, n0, lane, kc);
        int oRZ = gate ? oZS : oRS;
#pragma unroll
        for (int f = 0; f < 16; f++) {
            int mf = f >> 3, ng = f & 7;
            int colb = n0 + ng * 8 + lc;
            float b0 = *(float*)(dsm + oBIA + colb * 16 + gate * 4);
            float b1 = *(float*)(dsm + oBIA + colb * 16 + 16 + gate * 4);
#pragma unroll
            for (int hp = 0; hp < 2; hp++) {
                int row = m0 + mf * 16 + lr + hp * 8;
                float v0 = fsig(acc[f][hp * 2] + b0);
                float v1 = fsig(acc[f][hp * 2 + 1] + b1);
                ushort2 u = make_ushort2((unsigned short)(v0 * 65535.f + 0.5f),
                                         (unsigned short)(v1 * 65535.f + 0.5f));
                *(ushort2*)(dsm + oRZ + row * 256 + colb * 2) = u;
            }
        }
        __syncthreads();
        // stage next gate's B (gate0 -> g1 ; gate1 -> g2)
        const __half* wh2 = whT + (size_t)(gate + 1) * 32768;
        const __half* wi2 = wiT + (size_t)(gate + 1) * 8192;
        stage128(S + oBH, wh2, 128, tid);
        stage128(S + oBL, wh2 + 16384, 128, tid);
        stage32s(S + oBXH, wi2, tid);
        stage32s(S + oBXL, wi2 + 4096, tid);
        cpwait(); __syncthreads();
    }

    // ---- gate n: gh2 (K=128) and gi2 (K=32) separate ----
    zacc(acc);
    for (int kc = 0; kc < 8; kc++)
        kstep128(acc, S + oAH, S + oAL, S + oBH, S + oBL, m0, n0, lane, kc);
    float acc2[16][4];
    zacc(acc2);
    for (int kc = 0; kc < 2; kc++)
        kstep32(acc2, S + oAXH, S + oAXL, S + oBXH, S + oBXL, m0, n0, lane, kc);

    // ---- epilogue ----
    const float Q = 1.0f / 65535.0f;
#pragma unroll
    for (int f = 0; f < 16; f++) {
        int mf = f >> 3, ng = f & 7;
        int colb = n0 + ng * 8 + lc;
        const float* bp = (const float*)(dsm + oBIA + colb * 16);
        const float* bq = (const float*)(dsm + oBIA + colb * 16 + 16);
#pragma unroll
        for (int hp = 0; hp < 2; hp++) {
            int row = m0 + mf * 16 + lr + hp * 8;
            ushort2 r2 = *(ushort2*)(dsm + oRS + row * 256 + colb * 2);
            ushort2 z2 = *(ushort2*)(dsm + oZS + row * 256 + colb * 2);
            u32 aoff = (u32)row * 256u + (u32)((((colb >> 3) ^ (row & 7)) << 4)) + (colb & 7) * 2;
            __half2 hhv = *(__half2*)(dsm + oAH + aoff);
            __half2 hlv = *(__half2*)(dsm + oAL + aoff);
            float rr0 = r2.x * Q, rr1 = r2.y * Q;
            float zz0 = z2.x * Q, zz1 = z2.y * Q;
            float nn0 = ftanh(acc2[f][hp * 2]     + bp[3] + rr0 * (acc[f][hp * 2]     + bp[2]));
            float nn1 = ftanh(acc2[f][hp * 2 + 1] + bq[3] + rr1 * (acc[f][hp * 2 + 1] + bq[2]));
            float h0 = __half2float(__low2half(hhv)) + __half2float(__low2half(hlv));
            float h1 = __half2float(__high2half(hhv)) + __half2float(__high2half(hlv));
            float o0 = (1.0f - zz0) * nn0 + zz0 * h0;
            float o1 = (1.0f - zz1) * nn1 + zz1 * h1;
            __half H0, L0, H1, L1;
            wsplit(o0, H0, L0); wsplit(o1, H1, L1);
            size_t go = (size_t)(row0 + row) * 128 + colb;
            *(__half2*)(oh + go) = __halves2half2(H0, H1);
            *(__half2*)(ol + go) = __halves2half2(L0, L1);
        }
    }
}

// ===================== comb (tensor) =====================
#define cAH  0
#define cAL  32768
#define cA2H 65536
#define cA2L 98304
#define cBH  131072
#define cBL  163840
#define COMB_DS 196608

__global__ __launch_bounds__(256)
void comb_k(const __half* __restrict__ fh, const __half* __restrict__ fl,
            const __half* __restrict__ ah, const __half* __restrict__ al,
            const __half* __restrict__ ufT, const __half* __restrict__ uaT,
            const float* __restrict__ ufb, const float* __restrict__ uab,
            __half* __restrict__ oh, __half* __restrict__ ol)
{
    extern __shared__ char dsm[];
    const u32 S = smaddr(dsm);
    const int tid = threadIdx.x, lane = tid & 31, wid = tid >> 5;
    const int row0 = blockIdx.x * 128;
    const int m0 = (wid & 3) * 32, n0 = (wid >> 2) * 64;

    stage128(S + cAH, fh + (size_t)row0 * 128, 128, tid);
    stage128(S + cAL, fl + (size_t)row0 * 128, 128, tid);
    stage128(S + cA2H, ah + (size_t)row0 * 128, 128, tid);
    stage128(S + cA2L, al + (size_t)row0 * 128, 128, tid);
    stage128(S + cBH, ufT, 128, tid);
    stage128(S + cBL, ufT + 16384, 128, tid);
    cpwait(); __syncthreads();

    float acc[16][4];
    zacc(acc);
    for (int kc = 0; kc < 8; kc++)
        kstep128(acc, S + cAH, S + cAL, S + cBH, S + cBL, m0, n0, lane, kc);
    __syncthreads();
    stage128(S + cBH, uaT, 128, tid);
    stage128(S + cBL, uaT + 16384, 128, tid);
    cpwait(); __syncthreads();
    for (int kc = 0; kc < 8; kc++)
        kstep128(acc, S + cA2H, S + cA2L, S + cBH, S + cBL, m0, n0, lane, kc);

    const int lr = lane >> 2, lc = 2 * (lane & 3);
#pragma unroll
    for (int f = 0; f < 16; f++) {
        int mf = f >> 3, ng = f & 7;
        int colb = n0 + ng * 8 + lc;
        float b0 = __ldg(ufb + colb) + __ldg(uab + colb);
        float b1 = __ldg(ufb + colb + 1) + __ldg(uab + colb + 1);
#pragma unroll
        for (int hp = 0; hp < 2; hp++) {
            int row = m0 + mf * 16 + lr + hp * 8;
            float o0 = ftanh(acc[f][hp * 2] + b0);
            float o1 = ftanh(acc[f][hp * 2 + 1] + b1);
            __half H0, L0, H1, L1;
            wsplit(o0, H0, L0); wsplit(o1, H1, L1);
            size_t go = (size_t)(row0 + row) * 128 + colb;
            *(__half2*)(oh + go) = __halves2half2(H0, H1);
            *(__half2*)(ol + go) = __halves2half2(L0, L1);
        }
    }
}

// ===================== node (tensor + fused softmax) =====================
#define nAH 0
#define nAL 32768
#define nBH 65536
#define nBL 73728
#define nPR 81920
#define NODE_DS 98304

__global__ __launch_bounds__(256)
void node_k(const __half* __restrict__ hh, const __half* __restrict__ hl,
            const __half* __restrict__ h2oT, const float* __restrict__ b,
            float* __restrict__ pred, __half* __restrict__ ph, __half* __restrict__ pl)
{
    extern __shared__ char dsm[];
    const u32 S = smaddr(dsm);
    const int tid = threadIdx.x, lane = tid & 31, wid = tid >> 5;
    const int row0 = blockIdx.x * 128;
    const int m0 = wid * 16;

    stage128(S + nAH, hh + (size_t)row0 * 128, 128, tid);
    stage128(S + nAL, hl + (size_t)row0 * 128, 128, tid);
    stage128(S + nBH, h2oT, 32, tid);
    stage128(S + nBL, h2oT + 4096, 32, tid);
    cpwait(); __syncthreads();

    float acc[4][4];
#pragma unroll
    for (int f = 0; f < 4; f++)
#pragma unroll
        for (int i = 0; i < 4; i++) acc[f][i] = 0.0f;

    for (int kc = 0; kc < 8; kc++) {
        u32 ahr[4], alr[4];
        ldmA128(ahr, S + nAH, m0, lane, kc);
        ldmA128(alr, S + nAL, m0, lane, kc);
#pragma unroll
        for (int G = 0; G < 2; G++) {
            u32 bh[4], bl[4];
            ldmB128(bh, S + nBH, G * 16, lane, kc);
            ldmB128(bl, S + nBL, G * 16, lane, kc);
            mmaf(acc[G * 2], ahr, bh);     mmaf(acc[G * 2 + 1], ahr, bh + 2);
            mmaf(acc[G * 2], ahr, bl);     mmaf(acc[G * 2 + 1], ahr, bl + 2);
            mmaf(acc[G * 2], alr, bh);     mmaf(acc[G * 2 + 1], alr, bh + 2);
        }
    }
    const int lr = lane >> 2, lc = 2 * (lane & 3);
#pragma unroll
    for (int f = 0; f < 4; f++) {
#pragma unroll
        for (int i = 0; i < 4; i++) {
            int row = m0 + lr + (i >> 1) * 8;
            int col = f * 8 + lc + (i & 1);
            *(float*)(dsm + nPR + (row * 32 + col) * 4) = acc[f][i] + __ldg(b + col);
        }
    }
    __syncthreads();
    if (tid < 128) {
        int row = tid;
        const float* pr = (const float*)(dsm + nPR + row * 128);
        float v[32], mx = -1e30f;
#pragma unroll
        for (int i = 0; i < 32; i++) { v[i] = pr[i]; mx = fmaxf(mx, v[i]); }
        float e[32], sum = 0.0f;
#pragma unroll
        for (int i = 0; i < 32; i++) { e[i] = __expf(v[i] - mx); sum += e[i]; }
        float inv = __fdividef(1.0f, sum);
        size_t go = (size_t)(row0 + row) * 32;
        float4* pg = (float4*)(pred + go);
#pragma unroll
        for (int q = 0; q < 8; q++)
            pg[q] = make_float4(v[4 * q], v[4 * q + 1], v[4 * q + 2], v[4 * q + 3]);
#pragma unroll
        for (int j = 0; j < 16; j++) {
            float p0 = e[2 * j] * inv, p1 = e[2 * j + 1] * inv;
            __half H0, L0, H1, L1;
            wsplit(p0, H0, L0); wsplit(p1, H1, L1);
            *(__half2*)(ph + go + 2 * j) = __halves2half2(H0, H1);
            *(__half2*)(pl + go + 2 * j) = __halves2half2(L0, L1);
        }
    }
}

// ===================== host =====================
namespace {
struct LCtx {
    const __half *wt;
    const float *h2o_b;
    const float *anc_bi, *anc_bh, *frat_bi, *frat_bh;
    const float *ua_b, *uf_b;
    __half *hAh, *hAl, *hFh, *hFl, *prh, *prl;
    float* out;
    int idx;
};

void rec(LCtx& c, int L, int d)
{
    size_t hL = (size_t)L * BATCH * HD, hL1 = (size_t)(L + 1) * BATCH * HD;
    size_t pL = (size_t)L * BATCH * OD, pL1 = (size_t)(L + 1) * BATCH * OD;

    node_k<<<BATCH / 128, 256, NODE_DS>>>(c.hAh + hL, c.hAl + hL,
                                          c.wt + W_H2O, c.h2o_b,
                                          c.out + (size_t)c.idx * BATCH * OD,
                                          c.prh + pL, c.prl + pL);
    c.idx++;
    if (d == 0) return;

    gru_k<<<BATCH / 128, 256, GRU_DS>>>(c.prh + pL, c.prl + pL,
                                        c.hAh + hL, c.hAl + hL,
                                        c.wt + W_ANC_WH, c.wt + W_ANC_WI,
                                        c.anc_bi, c.anc_bh,
                                        c.hAh + hL1, c.hAl + hL1);
    rec(c, L + 1, d - 1);

    size_t fL = (size_t)L * BATCH * HD;
    gru_k<<<BATCH / 128, 256, GRU_DS>>>(c.prh + pL1, c.prl + pL1,
                                        c.hAh + hL1, c.hAl + hL1,
                                        c.wt + W_FRAT_WH, c.wt + W_FRAT_WI,
                                        c.frat_bi, c.frat_bh,
                                        c.hFh + fL, c.hFl + fL);

    comb_k<<<BATCH / 128, 256, COMB_DS>>>(c.hFh + fL, c.hFl + fL,
                                          c.hAh + hL, c.hAl + hL,
                                          c.wt + W_UF, c.wt + W_UA,
                                          c.uf_b, c.ua_b,
                                          c.hAh + hL1, c.hAl + hL1);
    rec(c, L + 1, d - 1);
}
} // namespace

extern "C" void kernel_launch(void* const* d_in, const int* in_sizes, int n_in,
                              void* d_out, int out_size)
{
    const float* z       = (const float*)d_in[0];
    const float* z2h_w   = (const float*)d_in[1];
    const float* z2h_b   = (const float*)d_in[2];
    const float* h2o_w   = (const float*)d_in[3];
    const float* h2o_b   = (const float*)d_in[4];
    const float* anc_wi  = (const float*)d_in[5];
    const float* anc_wh  = (const float*)d_in[6];
    const float* anc_bi  = (const float*)d_in[7];
    const float* anc_bh  = (const float*)d_in[8];
    const float* frat_wi = (const float*)d_in[9];
    const float* frat_wh = (const float*)d_in[10];
    const float* frat_bi = (const float*)d_in[11];
    const float* frat_bh = (const float*)d_in[12];
    const float* ua_w    = (const float*)d_in[13];
    const float* ua_b    = (const float*)d_in[14];
    const float* uf_w    = (const float*)d_in[15];
    const float* uf_b    = (const float*)d_in[16];

    static bool attr_done = false;
    if (!attr_done) {
        cudaFuncSetAttribute(gru_k,  cudaFuncAttributeMaxDynamicSharedMemorySize, GRU_DS);
        cudaFuncSetAttribute(comb_k, cudaFuncAttributeMaxDynamicSharedMemorySize, COMB_DS);
        cudaFuncSetAttribute(node_k, cudaFuncAttributeMaxDynamicSharedMemorySize, NODE_DS);
        attr_done = true;
    }

    __half *wt, *hAh, *hAl, *hFh, *hFl, *prh, *prl;
    cudaGetSymbolAddress((void**)&wt, g_wt);
    cudaGetSymbolAddress((void**)&hAh, g_hAh);
    cudaGetSymbolAddress((void**)&hAl, g_hAl);
    cudaGetSymbolAddress((void**)&hFh, g_hFh);
    cudaGetSymbolAddress((void**)&hFl, g_hFl);
    cudaGetSymbolAddress((void**)&prh, g_prh);
    cudaGetSymbolAddress((void**)&prl, g_prl);

    k_prep<<<128, 256>>>(anc_wi, anc_wh, frat_wi, frat_wh, uf_w, ua_w, h2o_w);
    init_k<<<BATCH / 16, 128>>>(z, z2h_w, z2h_b, hAh, hAl);

    LCtx c;
    c.wt = wt; c.h2o_b = h2o_b;
    c.anc_bi = anc_bi; c.anc_bh = anc_bh;
    c.frat_bi = frat_bi; c.frat_bh = frat_bh;
    c.ua_b = ua_b; c.uf_b = uf_b;
    c.hAh = hAh; c.hAl = hAl; c.hFh = hFh; c.hFl = hFl;
    c.prh = prh; c.prl = prl;
    c.out = (float*)d_out;
    c.idx = 0;
    rec(c, 0, DEPTH);
}